// round 11
// baseline (speedup 1.0000x reference)
#include <cuda_runtime.h>
#include <cstdint>

#define TSTEPS  512
#define BATCH   64
#define IN_DIM  512
#define HID     1024
#define NCTA    128
#define COLS    32                 // z-cols per CTA = 4 gates x 8 hid cols
#define HPC     8
#define CTA_W_F2 24576             // 192 kpanels * 128 float2
#define ZR_STRIDE 34
#define ZR_BUF   (64 * ZR_STRIDE)  // 2176 floats
#define WH_SMEM_B 131072           // 128 h-panels * 1KB
#define WX_SMEM_B 65536            // 64 x-panels * 1KB
#define SMEM_PERSIST (WH_SMEM_B + 4 * ZR_BUF * 4 + 128)   // ~166KB
#define SMEM_ZX      (WX_SMEM_B + 4 * ZR_BUF * 4 + 128)   // ~100KB

// ---- static device scratch (no allocations) ----
__device__ float2   g_Wp[(size_t)NCTA * CTA_W_F2];       // packed tf32 W (~25MB)
__device__ float4   g_xp[(size_t)TSTEPS * 8192];         // x, fragment-permuted (~67MB)
__device__ float4   g_zx4[(size_t)NCTA * TSTEPS * 512];  // zx: one float4/thread (536MB)
__device__ float4   g_hp[2 * 16384];                     // h, fragment-permuted, dbl-buffered
__device__ float    g_bp[NCTA * COLS];                   // packed bias
__device__ unsigned g_flag[NCTA];                        // per-CTA h-publication flags

// ---------------- helpers ----------------
__device__ __forceinline__ float tf32r(float x) {
    unsigned r;
    asm("cvt.rna.tf32.f32 %0, %1;" : "=r"(r) : "f"(x));
    return __uint_as_float(r);
}
__device__ __forceinline__ void mma_tf32(float* c, float a0, float a1, float a2, float a3,
                                         float b0, float b1) {
    asm volatile(
        "mma.sync.aligned.m16n8k8.row.col.f32.tf32.tf32.f32 "
        "{%0,%1,%2,%3},{%4,%5,%6,%7},{%8,%9},{%0,%1,%2,%3};"
        : "+f"(c[0]), "+f"(c[1]), "+f"(c[2]), "+f"(c[3])
        : "r"(__float_as_uint(a0)), "r"(__float_as_uint(a1)),
          "r"(__float_as_uint(a2)), "r"(__float_as_uint(a3)),
          "r"(__float_as_uint(b0)), "r"(__float_as_uint(b1)));
}
__device__ __forceinline__ float4 ldcg4(const float4* p) {
    float4 v;
    asm volatile("ld.global.cg.v4.f32 {%0,%1,%2,%3}, [%4];"
                 : "=f"(v.x), "=f"(v.y), "=f"(v.z), "=f"(v.w) : "l"(p));
    return v;
}
// Per-panel producer gate: one broadcast acquire load; nanosleep backoff only if blocked.
__device__ __forceinline__ void wait_flag(const unsigned* f, unsigned t) {
    unsigned v;
    asm volatile("ld.acquire.gpu.global.u32 %0, [%1];" : "=r"(v) : "l"(f) : "memory");
    while (v < t) {
        __nanosleep(60);
        asm volatile("ld.acquire.gpu.global.u32 %0, [%1];" : "=r"(v) : "l"(f) : "memory");
    }
}
// W fragments for one k-panel: 4 conflict-free LDS.64
__device__ __forceinline__ void load_w(float2* bq, const float2* Ws, int p, int gid, int ktid) {
    const float2* wrow = Ws + p * 128 + gid * 4 + ktid;
    bq[0] = wrow[0];
    bq[1] = wrow[32];
    bq[2] = wrow[64];
    bq[3] = wrow[96];
}
__device__ __forceinline__ void mma8(float (&acc)[2][4][4], const float4* f, const float2* bq) {
#pragma unroll
    for (int mt = 0; mt < 2; ++mt)
#pragma unroll
        for (int n = 0; n < 4; ++n)
            mma_tf32(acc[mt][n], f[mt].x, f[mt].y, f[mt].z, f[mt].w, bq[n].x, bq[n].y);
}
__device__ __forceinline__ void store_acc(float* zr, const float (&acc)[2][4][4],
                                          int rb, int gid, int ktid) {
#pragma unroll
    for (int mt = 0; mt < 2; ++mt)
#pragma unroll
        for (int n = 0; n < 4; ++n) {
            int r = rb + mt * 16 + gid, cb = n * 8 + 2 * ktid;
            *(float2*)(zr + r * ZR_STRIDE + cb)       = make_float2(acc[mt][n][0], acc[mt][n][1]);
            *(float2*)(zr + (r + 8) * ZR_STRIDE + cb) = make_float2(acc[mt][n][2], acc[mt][n][3]);
        }
}
__device__ __forceinline__ void load_add(const float* zr, float (&acc)[2][4][4],
                                         int rb, int gid, int ktid) {
#pragma unroll
    for (int mt = 0; mt < 2; ++mt)
#pragma unroll
        for (int n = 0; n < 4; ++n) {
            int r = rb + mt * 16 + gid, cb = n * 8 + 2 * ktid;
            float2 v0 = *(const float2*)(zr + r * ZR_STRIDE + cb);
            float2 v1 = *(const float2*)(zr + (r + 8) * ZR_STRIDE + cb);
            acc[mt][n][0] += v0.x; acc[mt][n][1] += v0.y;
            acc[mt][n][2] += v1.x; acc[mt][n][3] += v1.y;
        }
}
__device__ __forceinline__ float sigmoid_f(float z) {
    return 1.0f / (1.0f + __expf(-z));
}
__device__ __forceinline__ float tanh_f(float z) {
    return 1.0f - 2.0f / (1.0f + __expf(2.0f * z));
}

// ---------------- prep kernels ----------------
// Pack W into per-CTA mma-B-fragment order (tf32-rounded) + bias. (R4/R6-proven layout.)
__global__ void prep_w(const float* __restrict__ Wf, const float* __restrict__ bf,
                       const float* __restrict__ Wi, const float* __restrict__ bi,
                       const float* __restrict__ Wg, const float* __restrict__ bg,
                       const float* __restrict__ Wo, const float* __restrict__ bo) {
    int idx = blockIdx.x * blockDim.x + threadIdx.x;
    if (idx < NCTA * COLS) {
        int cta = idx / COLS, ncol = idx % COLS;
        int gate = ncol >> 3, cc = ncol & 7;
        const float* bsrc = gate == 0 ? bf : gate == 1 ? bi : gate == 2 ? bg : bo;
        g_bp[idx] = bsrc[cta * HPC + cc];
    }
    if (idx >= NCTA * CTA_W_F2) return;
    int cta  = idx / CTA_W_F2;
    int rem  = idx % CTA_W_F2;
    int gk   = rem >> 7;
    int r2   = rem & 127;
    int ncol = r2 >> 2;        // n*8 + gid
    int ktid = r2 & 3;
    int gate = ncol >> 3, cc = ncol & 7;
    int col  = cta * HPC + cc;
    int k0   = gk * 8;
    const float* Wsrc = gate == 0 ? Wf : gate == 1 ? Wi : gate == 2 ? Wg : Wo;
    float v0 = Wsrc[(size_t)(k0 + ktid) * HID + col];
    float v1 = Wsrc[(size_t)(k0 + ktid + 4) * HID + col];
    g_Wp[idx] = make_float2(tf32r(v0), tf32r(v1));
}

// Permute x into fragment-order float4 slots, tf32-rounded. (R4-proven.)
__global__ void prep_xp(const float* __restrict__ x) {
    __shared__ float tile[16 * 132];
    int bid = blockIdx.x;
    int mt = bid & 3, kg = (bid >> 2) & 3, t = bid >> 4;
    const float* src = x + (size_t)t * BATCH * IN_DIM + (size_t)(mt * 16) * IN_DIM + kg * 128;
    for (int i = threadIdx.x; i < 16 * 32; i += 256) {
        int r = i >> 5, c4 = (i & 31) * 4;
        float4 v = *(const float4*)(src + (size_t)r * IN_DIM + c4);
        tile[r * 132 + c4]     = v.x;
        tile[r * 132 + c4 + 1] = v.y;
        tile[r * 132 + c4 + 2] = v.z;
        tile[r * 132 + c4 + 3] = v.w;
    }
    __syncthreads();
    for (int o = threadIdx.x; o < 512; o += 256) {
        int pl = o >> 5, l = o & 31;
        int gid = l >> 2, kt = l & 3;
        int k0 = pl * 8;
        float4 v;
        v.x = tf32r(tile[gid * 132 + k0 + kt]);
        v.y = tf32r(tile[(gid + 8) * 132 + k0 + kt]);
        v.z = tf32r(tile[gid * 132 + k0 + kt + 4]);
        v.w = tf32r(tile[(gid + 8) * 132 + k0 + kt + 4]);
        g_xp[(size_t)(t * 64 + kg * 16 + pl) * 128 + mt * 32 + l] = v;
    }
}

__global__ void init_k() {
    int i = blockIdx.x * blockDim.x + threadIdx.x;
    float* h = (float*)g_hp;
    if (i < 2 * 65536) h[i] = 0.0f;
    if (i < NCTA) g_flag[i] = 0u;
}

// ---------------- zx precompute: zx[cta][t][tid] = {zf,zi,zg,zo} ----------------
__global__ void __launch_bounds__(512, 1) zx_kernel() {
    extern __shared__ char smem[];
    const float2* Ws = (const float2*)smem;            // 64 x-panels (64KB)
    float* zr = (float*)(smem + WX_SMEM_B);

    const int tid = threadIdx.x, w = tid >> 5, lane = tid & 31;
    const int gid = lane >> 2, ktid = lane & 3;
    const int kw = w >> 1, mh = w & 1;
    const int aoff = mh * 64 + lane;
    const int rb = mh * 32;
    const int cta = blockIdx.x & (NCTA - 1);
    const int tg  = blockIdx.x >> 7;                   // 16 groups x 32 steps

    {   // copy x-part of W (panels 0..63)
        const float4* src = (const float4*)(g_Wp + (size_t)cta * CTA_W_F2);
        float4* dst = (float4*)smem;
        for (int i = tid; i < 4096; i += 512) dst[i] = src[i];
    }
    const int eb = tid >> 3, ec = tid & 7;
    float b0 = g_bp[cta * COLS + ec];
    float b1 = g_bp[cta * COLS + 8 + ec];
    float b2 = g_bp[cta * COLS + 16 + ec];
    float b3 = g_bp[cta * COLS + 24 + ec];
    __syncthreads();

    const int px0 = kw * 8;
    for (int tt = 0; tt < 32; ++tt) {
        int t = tg * 32 + tt;
        float acc[2][4][4];
#pragma unroll
        for (int a = 0; a < 2; ++a)
#pragma unroll
            for (int b = 0; b < 4; ++b)
#pragma unroll
                for (int c = 0; c < 4; ++c) acc[a][b][c] = 0.0f;

        const float4* xpan = g_xp + (size_t)t * 8192 + (size_t)px0 * 128 + aoff;
        float4 fr[3][2];
        fr[0][0] = ldcg4(xpan);       fr[0][1] = ldcg4(xpan + 32);
        fr[1][0] = ldcg4(xpan + 128); fr[1][1] = ldcg4(xpan + 160);
        float2 bq[2][4];
        load_w(bq[0], Ws, px0, gid, ktid);
#pragma unroll
        for (int j = 0; j < 8; ++j) {
            if (j < 6) {
                const float4* p = xpan + (size_t)(j + 2) * 128;
                fr[(j + 2) % 3][0] = ldcg4(p);
                fr[(j + 2) % 3][1] = ldcg4(p + 32);
            }
            if (j < 7) load_w(bq[(j + 1) & 1], Ws, px0 + j + 1, gid, ktid);
            mma8(acc, fr[j % 3], bq[j & 1]);
        }

        if (kw >= 4) store_acc(zr + (size_t)(kw - 4) * ZR_BUF, acc, rb, gid, ktid);
        __syncthreads();
        if (kw < 4) {
            load_add(zr + (size_t)kw * ZR_BUF, acc, rb, gid, ktid);
            store_acc(zr + (size_t)kw * ZR_BUF, acc, rb, gid, ktid);
        }
        __syncthreads();

        {   // sum 4 bufs + bias, store zx as one float4 per thread
            float zf = b0, zi = b1, zg = b2, zo = b3;
#pragma unroll
            for (int u = 0; u < 4; ++u) {
                const float* zb = zr + u * ZR_BUF + eb * ZR_STRIDE;
                zf += zb[ec];
                zi += zb[8 + ec];
                zg += zb[16 + ec];
                zo += zb[24 + ec];
            }
            g_zx4[((size_t)cta * TSTEPS + t) * 512 + tid] = make_float4(zf, zi, zg, zo);
        }
        __syncthreads();
    }
}

// ---------------- persistent LSTM kernel (h-GEMM only, per-panel gating) ----------------
__global__ void __launch_bounds__(512, 1) lstm_persist(float* __restrict__ out) {
    extern __shared__ char smem[];
    const float2* Ws = (const float2*)smem;               // 128 h-panels (128KB)
    float* zr = (float*)(smem + WH_SMEM_B);               // 4 * ZR_BUF floats

    const int tid = threadIdx.x, w = tid >> 5, lane = tid & 31;
    const int gid = lane >> 2, ktid = lane & 3;
    const int kw = w >> 1, mh = w & 1;            // k-split 8 x m-split 2
    const int aoff = mh * 64 + lane;
    const int rb = mh * 32;
    const int cta = blockIdx.x;

    {   // one-time copy of h-part of W (panels 64..191 -> smem 0..127)
        const float4* src = (const float4*)(g_Wp + (size_t)cta * CTA_W_F2 + 8192);
        float4* dst = (float4*)smem;
        for (int i = tid; i < 8192; i += 512) dst[i] = src[i];
    }
    __syncthreads();

    float creg = 0.0f;                            // cell state (1 elem/thread)
    const int ph0 = kw * 16;                      // smem h-panel base
    const unsigned* fbase = g_flag + kw * 16;     // this warp's 16 producers
    const int eb = tid >> 3, ec = tid & 7;        // epilogue element
    const float4* zxb = g_zx4 + (size_t)cta * TSTEPS * 512 + tid;

    for (int t = 0; t < TSTEPS; ++t) {
        const unsigned tt = (unsigned)t;
        // zx for this step: one coalesced float4 (hidden behind GEMM)
        float4 zx = ldcg4(zxb + (size_t)t * 512);

        float acc[2][4][4];
#pragma unroll
        for (int a = 0; a < 2; ++a)
#pragma unroll
            for (int b = 0; b < 4; ++b)
#pragma unroll
                for (int c = 0; c < 4; ++c) acc[a][b][c] = 0.0f;

        const float4* hpan = g_hp + (size_t)((t - 1) & 1) * 16384 + (size_t)(kw * 16) * 128 + aoff;

        // ---- H GEMM: 16 panels, per-panel producer gating + 2-ahead prefetch ----
        float4 fr[3][2];
        wait_flag(fbase + 0, tt);
        fr[0][0] = ldcg4(hpan);       fr[0][1] = ldcg4(hpan + 32);
        wait_flag(fbase + 1, tt);
        fr[1][0] = ldcg4(hpan + 128); fr[1][1] = ldcg4(hpan + 160);
        float2 bq[2][4];
        load_w(bq[0], Ws, ph0, gid, ktid);
#pragma unroll
        for (int j = 0; j < 16; ++j) {
            if (j < 14) {
                wait_flag(fbase + j + 2, tt);
                const float4* p = hpan + (size_t)(j + 2) * 128;
                fr[(j + 2) % 3][0] = ldcg4(p);
                fr[(j + 2) % 3][1] = ldcg4(p + 32);
            }
            if (j < 15) load_w(bq[(j + 1) & 1], Ws, ph0 + j + 1, gid, ktid);
            mma8(acc, fr[j % 3], bq[j & 1]);
        }

        // ---- 2-round k-partial reduction ----
        if (kw >= 4) store_acc(zr + (size_t)(kw - 4) * ZR_BUF, acc, rb, gid, ktid);
        __syncthreads();
        if (kw < 4) {
            load_add(zr + (size_t)kw * ZR_BUF, acc, rb, gid, ktid);
            store_acc(zr + (size_t)kw * ZR_BUF, acc, rb, gid, ktid);
        }
        __syncthreads();

        // ---- fused gate epilogue ----
        {
            float zf = zx.x, zi = zx.y, zg = zx.z, zo = zx.w;
#pragma unroll
            for (int u = 0; u < 4; ++u) {
                const float* zb = zr + u * ZR_BUF + eb * ZR_STRIDE;
                zf += zb[ec];
                zi += zb[8 + ec];
                zg += zb[16 + ec];
                zo += zb[24 + ec];
            }
            float fg = sigmoid_f(zf);
            float ig = sigmoid_f(zi);
            float gg = tanh_f(zg);
            float og = sigmoid_f(zo);
            float cn = fg * creg + ig * gg;
            creg = cn;
            float h = og * tanh_f(cn);
            int hcol = cta * HPC + ec;
            out[(size_t)t * (BATCH * HID) + eb * HID + hcol] = h;
            // fragment-permuted tf32 h for next step's A operand
            int p   = hcol >> 3, j = hcol & 7;
            int mt  = eb >> 4, g8 = eb & 7, hh = (eb >> 3) & 1;
            int kt2 = j & 3, comp = ((j >> 2) << 1) | hh;
            ((float*)g_hp)[((size_t)(t & 1) * 16384 + (size_t)(p * 4 + mt) * 32 +
                            g8 * 4 + kt2) * 4 + comp] = tf32r(h);
            if (t == TSTEPS - 1) {
                size_t tail = (size_t)TSTEPS * BATCH * HID;
                out[tail + eb * HID + hcol] = h;
                out[tail + BATCH * HID + eb * HID + hcol] = cn;
            }
        }
        __syncthreads();   // h writes done; zr reusable

        // ---- publish h_t ----
        if (tid == 0) {
            __threadfence();
            asm volatile("st.release.gpu.global.u32 [%0], %1;"
                         :: "l"(g_flag + cta), "r"((unsigned)(t + 1)) : "memory");
        }
    }
}

// ---------------- host ----------------
extern "C" void kernel_launch(void* const* d_in, const int* in_sizes, int n_in,
                              void* d_out, int out_size) {
    const float* x  = (const float*)d_in[0];
    const float* Wf = (const float*)d_in[1];
    const float* bf = (const float*)d_in[2];
    const float* Wi = (const float*)d_in[3];
    const float* bi = (const float*)d_in[4];
    const float* Wg = (const float*)d_in[5];
    const float* bg = (const float*)d_in[6];
    const float* Wo = (const float*)d_in[7];
    const float* bo = (const float*)d_in[8];
    float* out = (float*)d_out;

    static int attr_done = 0;
    if (!attr_done) {
        cudaFuncSetAttribute(lstm_persist, cudaFuncAttributeMaxDynamicSharedMemorySize,
                             SMEM_PERSIST);
        cudaFuncSetAttribute(zx_kernel, cudaFuncAttributeMaxDynamicSharedMemorySize,
                             SMEM_ZX);
        attr_done = 1;
    }

    init_k<<<512, 256>>>();
    prep_w<<<(NCTA * CTA_W_F2 + 255) / 256, 256>>>(Wf, bf, Wi, bi, Wg, bg, Wo, bo);
    prep_xp<<<8192, 256>>>(x);
    zx_kernel<<<NCTA * 16, 512, SMEM_ZX>>>();
    lstm_persist<<<NCTA, 512, SMEM_PERSIST>>>(out);
}

// round 12
// speedup vs baseline: 1.8196x; 1.8196x over previous
#include <cuda_runtime.h>
#include <cstdint>

#define TSTEPS  512
#define BATCH   64
#define IN_DIM  512
#define HID     1024
#define NCTA    128
#define COLS    32                 // z-cols per CTA = 4 gates x 8 hid cols
#define HPC     8
#define CTA_W_F2 24576             // 192 kpanels * 128 float2
#define ZR_STRIDE 34
#define ZR_BUF   (64 * ZR_STRIDE)  // 2176 floats
#define W_SMEM_B 196608
#define SMEM_BYTES (W_SMEM_B + 4 * ZR_BUF * 4 + 128)   // 231552

// ---- static device scratch (no allocations) ----
__device__ float2   g_Wp[(size_t)NCTA * CTA_W_F2];     // packed tf32 W (~25MB)
__device__ float4   g_xp[(size_t)(TSTEPS + 1) * 8192]; // x, fragment-permuted (+1 step slack)
__device__ float4   g_hp[2 * 16384];                   // h, fragment-permuted, dbl-buffered
__device__ float    g_bp[NCTA * COLS];                 // packed bias
__device__ unsigned g_flag[NCTA];                      // per-CTA h-publication flags

// ---------------- helpers ----------------
__device__ __forceinline__ float tf32r(float x) {
    unsigned r;
    asm("cvt.rna.tf32.f32 %0, %1;" : "=r"(r) : "f"(x));
    return __uint_as_float(r);
}
__device__ __forceinline__ void mma_tf32(float* c, float a0, float a1, float a2, float a3,
                                         float b0, float b1) {
    asm volatile(
        "mma.sync.aligned.m16n8k8.row.col.f32.tf32.tf32.f32 "
        "{%0,%1,%2,%3},{%4,%5,%6,%7},{%8,%9},{%0,%1,%2,%3};"
        : "+f"(c[0]), "+f"(c[1]), "+f"(c[2]), "+f"(c[3])
        : "r"(__float_as_uint(a0)), "r"(__float_as_uint(a1)),
          "r"(__float_as_uint(a2)), "r"(__float_as_uint(a3)),
          "r"(__float_as_uint(b0)), "r"(__float_as_uint(b1)));
}
__device__ __forceinline__ float4 ldcg4(const float4* p) {
    float4 v;
    asm volatile("ld.global.cg.v4.f32 {%0,%1,%2,%3}, [%4];"
                 : "=f"(v.x), "=f"(v.y), "=f"(v.z), "=f"(v.w) : "l"(p));
    return v;
}
// Per-panel producer gate: single broadcast acquire-load; spins only when blocked.
__device__ __forceinline__ void wait_flag(const unsigned* f, unsigned t) {
    unsigned v;
    do {
        asm volatile("ld.acquire.gpu.global.u32 %0, [%1];" : "=r"(v) : "l"(f) : "memory");
    } while (v < t);
}
// W fragments for one k-panel: 4 conflict-free LDS.64
__device__ __forceinline__ void load_w(float2* bq, const float2* Ws, int p, int gid, int ktid) {
    const float2* wrow = Ws + p * 128 + gid * 4 + ktid;
    bq[0] = wrow[0];
    bq[1] = wrow[32];
    bq[2] = wrow[64];
    bq[3] = wrow[96];
}
__device__ __forceinline__ void mma8(float (&acc)[2][4][4], const float4* f, const float2* bq) {
#pragma unroll
    for (int mt = 0; mt < 2; ++mt)
#pragma unroll
        for (int n = 0; n < 4; ++n)
            mma_tf32(acc[mt][n], f[mt].x, f[mt].y, f[mt].z, f[mt].w, bq[n].x, bq[n].y);
}
__device__ __forceinline__ void store_acc(float* zr, const float (&acc)[2][4][4],
                                          int rb, int gid, int ktid) {
#pragma unroll
    for (int mt = 0; mt < 2; ++mt)
#pragma unroll
        for (int n = 0; n < 4; ++n) {
            int r = rb + mt * 16 + gid, cb = n * 8 + 2 * ktid;
            *(float2*)(zr + r * ZR_STRIDE + cb)       = make_float2(acc[mt][n][0], acc[mt][n][1]);
            *(float2*)(zr + (r + 8) * ZR_STRIDE + cb) = make_float2(acc[mt][n][2], acc[mt][n][3]);
        }
}
__device__ __forceinline__ void load_add(const float* zr, float (&acc)[2][4][4],
                                         int rb, int gid, int ktid) {
#pragma unroll
    for (int mt = 0; mt < 2; ++mt)
#pragma unroll
        for (int n = 0; n < 4; ++n) {
            int r = rb + mt * 16 + gid, cb = n * 8 + 2 * ktid;
            float2 v0 = *(const float2*)(zr + r * ZR_STRIDE + cb);
            float2 v1 = *(const float2*)(zr + (r + 8) * ZR_STRIDE + cb);
            acc[mt][n][0] += v0.x; acc[mt][n][1] += v0.y;
            acc[mt][n][2] += v1.x; acc[mt][n][3] += v1.y;
        }
}
__device__ __forceinline__ float sigmoid_f(float z) {
    return 1.0f / (1.0f + __expf(-z));
}
__device__ __forceinline__ float tanh_f(float z) {
    return 1.0f - 2.0f / (1.0f + __expf(2.0f * z));
}

// ---------------- prep kernels ----------------
// Pack W into per-CTA mma-B-fragment order (tf32-rounded) + bias. (R4/R6-proven layout.)
__global__ void prep_w(const float* __restrict__ Wf, const float* __restrict__ bf,
                       const float* __restrict__ Wi, const float* __restrict__ bi,
                       const float* __restrict__ Wg, const float* __restrict__ bg,
                       const float* __restrict__ Wo, const float* __restrict__ bo) {
    int idx = blockIdx.x * blockDim.x + threadIdx.x;
    if (idx < NCTA * COLS) {
        int cta = idx / COLS, ncol = idx % COLS;
        int gate = ncol >> 3, cc = ncol & 7;
        const float* bsrc = gate == 0 ? bf : gate == 1 ? bi : gate == 2 ? bg : bo;
        g_bp[idx] = bsrc[cta * HPC + cc];
    }
    if (idx >= NCTA * CTA_W_F2) return;
    int cta  = idx / CTA_W_F2;
    int rem  = idx % CTA_W_F2;
    int gk   = rem >> 7;
    int r2   = rem & 127;
    int ncol = r2 >> 2;        // n*8 + gid
    int ktid = r2 & 3;
    int gate = ncol >> 3, cc = ncol & 7;
    int col  = cta * HPC + cc;
    int k0   = gk * 8;
    const float* Wsrc = gate == 0 ? Wf : gate == 1 ? Wi : gate == 2 ? Wg : Wo;
    float v0 = Wsrc[(size_t)(k0 + ktid) * HID + col];
    float v1 = Wsrc[(size_t)(k0 + ktid + 4) * HID + col];
    g_Wp[idx] = make_float2(tf32r(v0), tf32r(v1));
}

// Permute x into fragment-order float4 slots, tf32-rounded. (R4-proven.)
__global__ void prep_xp(const float* __restrict__ x) {
    __shared__ float tile[16 * 132];
    int bid = blockIdx.x;
    int mt = bid & 3, kg = (bid >> 2) & 3, t = bid >> 4;
    const float* src = x + (size_t)t * BATCH * IN_DIM + (size_t)(mt * 16) * IN_DIM + kg * 128;
    for (int i = threadIdx.x; i < 16 * 32; i += 256) {
        int r = i >> 5, c4 = (i & 31) * 4;
        float4 v = *(const float4*)(src + (size_t)r * IN_DIM + c4);
        tile[r * 132 + c4]     = v.x;
        tile[r * 132 + c4 + 1] = v.y;
        tile[r * 132 + c4 + 2] = v.z;
        tile[r * 132 + c4 + 3] = v.w;
    }
    __syncthreads();
    for (int o = threadIdx.x; o < 512; o += 256) {
        int pl = o >> 5, l = o & 31;
        int gid = l >> 2, kt = l & 3;
        int k0 = pl * 8;
        float4 v;
        v.x = tf32r(tile[gid * 132 + k0 + kt]);
        v.y = tf32r(tile[(gid + 8) * 132 + k0 + kt]);
        v.z = tf32r(tile[gid * 132 + k0 + kt + 4]);
        v.w = tf32r(tile[(gid + 8) * 132 + k0 + kt + 4]);
        g_xp[(size_t)(t * 64 + kg * 16 + pl) * 128 + mt * 32 + l] = v;
    }
}

__global__ void init_k() {
    int i = blockIdx.x * blockDim.x + threadIdx.x;
    float* h = (float*)g_hp;
    if (i < 2 * 65536) h[i] = 0.0f;
    if (i < NCTA) g_flag[i] = 0u;
}

// ---------------- persistent LSTM kernel ----------------
__global__ void __launch_bounds__(512, 1) lstm_persist(float* __restrict__ out) {
    extern __shared__ char smem[];
    const float2* Ws = (const float2*)smem;               // 196608 B, fragment order
    float* zr = (float*)(smem + W_SMEM_B);                // 4 * ZR_BUF floats
    float* bias_s = (float*)(smem + W_SMEM_B + 4 * ZR_BUF * 4);

    const int tid = threadIdx.x, w = tid >> 5, lane = tid & 31;
    const int gid = lane >> 2, ktid = lane & 3;
    const int kw = w >> 1, mh = w & 1;            // k-split 8 x m-split 2
    const int aoff = mh * 64 + lane;
    const int rb = mh * 32;
    const int cta = blockIdx.x;

    {   // one-time W slice copy to smem (fragment order preserved)
        const float4* src = (const float4*)(g_Wp + (size_t)cta * CTA_W_F2);
        float4* dst = (float4*)smem;
        for (int i = tid; i < 12288; i += 512) dst[i] = src[i];
    }
    if (tid < COLS) bias_s[tid] = g_bp[cta * COLS + tid];
    __syncthreads();

    float creg = 0.0f;                            // cell state (1 elem/thread)
    const int px0 = kw * 8;                       // this warp's 8 x-panels
    const int ph0 = 64 + kw * 16;                 // this warp's 16 h-panels (W index)
    const unsigned* fbase = g_flag + kw * 16;     // this warp's 16 producers

    float4 fr[3][2];
    {   // initial x prefetch for t=0
        const float4* xp = g_xp + (size_t)px0 * 128 + aoff;
        fr[0][0] = ldcg4(xp);       fr[0][1] = ldcg4(xp + 32);
        fr[1][0] = ldcg4(xp + 128); fr[1][1] = ldcg4(xp + 160);
    }

    for (int t = 0; t < TSTEPS; ++t) {
        const unsigned tt = (unsigned)t;
        float acc[2][4][4];
#pragma unroll
        for (int a = 0; a < 2; ++a)
#pragma unroll
            for (int b = 0; b < 4; ++b)
#pragma unroll
                for (int c = 0; c < 4; ++c) acc[a][b][c] = 0.0f;

        const float4* xpan = g_xp + (size_t)t * 8192 + (size_t)px0 * 128 + aoff;
        const float4* hpan = g_hp + (size_t)((t - 1) & 1) * 16384 + (size_t)(kw * 16) * 128 + aoff;

        float2 bq[2][4];
        // ---- X phase (no h dependency; overlaps producer skew). fr[0..1] preloaded. ----
        load_w(bq[0], Ws, px0, gid, ktid);
#pragma unroll
        for (int j = 0; j < 8; ++j) {
            if (j < 6) {
                const float4* p = xpan + (size_t)(j + 2) * 128;
                fr[(j + 2) % 3][0] = ldcg4(p);
                fr[(j + 2) % 3][1] = ldcg4(p + 32);
            }
            if (j < 7) load_w(bq[(j + 1) & 1], Ws, px0 + j + 1, gid, ktid);
            mma8(acc, fr[j % 3], bq[j & 1]);
        }

        // ---- H phase: per-panel producer gating + 2-ahead prefetch ----
        if (t) wait_flag(fbase + 0, tt);
        fr[0][0] = ldcg4(hpan);       fr[0][1] = ldcg4(hpan + 32);
        if (t) wait_flag(fbase + 1, tt);
        fr[1][0] = ldcg4(hpan + 128); fr[1][1] = ldcg4(hpan + 160);
        load_w(bq[0], Ws, ph0, gid, ktid);
#pragma unroll
        for (int j = 0; j < 16; ++j) {
            if (j < 14) {
                if (t) wait_flag(fbase + j + 2, tt);
                const float4* p = hpan + (size_t)(j + 2) * 128;
                fr[(j + 2) % 3][0] = ldcg4(p);
                fr[(j + 2) % 3][1] = ldcg4(p + 32);
            }
            if (j < 15) load_w(bq[(j + 1) & 1], Ws, ph0 + j + 1, gid, ktid);
            mma8(acc, fr[j % 3], bq[j & 1]);
        }

        // ---- cross-step x prefetch (lands during reduce+epilogue; g_xp padded) ----
        {
            const float4* xn = g_xp + (size_t)(t + 1) * 8192 + (size_t)px0 * 128 + aoff;
            fr[0][0] = ldcg4(xn);       fr[0][1] = ldcg4(xn + 32);
            fr[1][0] = ldcg4(xn + 128); fr[1][1] = ldcg4(xn + 160);
        }

        // ---- 2-round k-partial reduction (8 -> 4 in smem, 4 -> 1 in epilogue) ----
        if (kw >= 4) store_acc(zr + (size_t)(kw - 4) * ZR_BUF, acc, rb, gid, ktid);
        __syncthreads();
        if (kw < 4) {
            load_add(zr + (size_t)kw * ZR_BUF, acc, rb, gid, ktid);
            store_acc(zr + (size_t)kw * ZR_BUF, acc, rb, gid, ktid);
        }
        __syncthreads();

        // ---- fused gate epilogue: 512 elements, 1 per thread; sums 4 bufs ----
        {
            int b  = tid >> 3, cx = tid & 7;
            float zf = bias_s[cx], zi = bias_s[8 + cx];
            float zg = bias_s[16 + cx], zo = bias_s[24 + cx];
#pragma unroll
            for (int u = 0; u < 4; ++u) {
                const float* zb = zr + u * ZR_BUF + b * ZR_STRIDE;
                zf += zb[cx];
                zi += zb[8 + cx];
                zg += zb[16 + cx];
                zo += zb[24 + cx];
            }
            float fg = sigmoid_f(zf);
            float ig = sigmoid_f(zi);
            float gg = tanh_f(zg);
            float og = sigmoid_f(zo);
            float cn = fg * creg + ig * gg;
            creg = cn;
            float h = og * tanh_f(cn);
            int hcol = cta * HPC + cx;
            out[(size_t)t * (BATCH * HID) + b * HID + hcol] = h;
            // fragment-permuted tf32 h for next step's A operand
            int p   = hcol >> 3, j = hcol & 7;
            int mt  = b >> 4, g8 = b & 7, hh = (b >> 3) & 1;
            int kt2 = j & 3, comp = ((j >> 2) << 1) | hh;
            ((float*)g_hp)[((size_t)(t & 1) * 16384 + (size_t)(p * 4 + mt) * 32 +
                            g8 * 4 + kt2) * 4 + comp] = tf32r(h);
            if (t == TSTEPS - 1) {
                size_t tail = (size_t)TSTEPS * BATCH * HID;
                out[tail + b * HID + hcol] = h;
                out[tail + BATCH * HID + b * HID + hcol] = cn;
            }
        }
        __syncthreads();   // h writes of all threads done; zr reusable

        // ---- publish h_t (release flag; consumers acquire) ----
        if (tid == 0) {
            __threadfence();
            asm volatile("st.release.gpu.global.u32 [%0], %1;"
                         :: "l"(g_flag + cta), "r"((unsigned)(t + 1)) : "memory");
        }
    }
}

// ---------------- host ----------------
extern "C" void kernel_launch(void* const* d_in, const int* in_sizes, int n_in,
                              void* d_out, int out_size) {
    const float* x  = (const float*)d_in[0];
    const float* Wf = (const float*)d_in[1];
    const float* bf = (const float*)d_in[2];
    const float* Wi = (const float*)d_in[3];
    const float* bi = (const float*)d_in[4];
    const float* Wg = (const float*)d_in[5];
    const float* bg = (const float*)d_in[6];
    const float* Wo = (const float*)d_in[7];
    const float* bo = (const float*)d_in[8];
    float* out = (float*)d_out;

    static int attr_done = 0;
    if (!attr_done) {
        cudaFuncSetAttribute(lstm_persist, cudaFuncAttributeMaxDynamicSharedMemorySize,
                             SMEM_BYTES);
        attr_done = 1;
    }

    init_k<<<512, 256>>>();
    prep_w<<<(NCTA * CTA_W_F2 + 255) / 256, 256>>>(Wf, bf, Wi, bi, Wg, bg, Wo, bo);
    prep_xp<<<8192, 256>>>(x);
    lstm_persist<<<NCTA, 512, SMEM_BYTES>>>(out);
}

// round 13
// speedup vs baseline: 2.1321x; 1.1717x over previous
#include <cuda_runtime.h>
#include <cstdint>

#define TSTEPS  512
#define BATCH   64
#define IN_DIM  512
#define HID     1024
#define NCTA    128
#define COLS    32                 // z-cols per CTA = 4 gates x 8 hid cols
#define HPC     8
#define CTA_W_F2 24576             // 192 kpanels * 128 float2
#define ZR_STRIDE 34
#define ZR_BUF   (64 * ZR_STRIDE)  // 2176 floats
#define W_SMEM_B 196608
#define SMEM_BYTES (W_SMEM_B + 4 * ZR_BUF * 4 + 128)   // 231552

// ---- static device scratch (no allocations) ----
__device__ float2   g_Wp[(size_t)NCTA * CTA_W_F2];     // packed tf32 W (~25MB)
__device__ float4   g_xp[(size_t)(TSTEPS + 1) * 8192]; // x, fragment-permuted (+1 step slack)
__device__ float4   g_hp[2 * 16384];                   // h, fragment-permuted, dbl-buffered
__device__ float    g_bp[NCTA * COLS];                 // packed bias
__device__ unsigned g_flag[NCTA];                      // per-CTA h-publication flags

// ---------------- helpers ----------------
__device__ __forceinline__ float tf32r(float x) {
    unsigned r;
    asm("cvt.rna.tf32.f32 %0, %1;" : "=r"(r) : "f"(x));
    return __uint_as_float(r);
}
__device__ __forceinline__ void mma_tf32(float* c, float a0, float a1, float a2, float a3,
                                         float b0, float b1) {
    asm volatile(
        "mma.sync.aligned.m16n8k8.row.col.f32.tf32.tf32.f32 "
        "{%0,%1,%2,%3},{%4,%5,%6,%7},{%8,%9},{%0,%1,%2,%3};"
        : "+f"(c[0]), "+f"(c[1]), "+f"(c[2]), "+f"(c[3])
        : "r"(__float_as_uint(a0)), "r"(__float_as_uint(a1)),
          "r"(__float_as_uint(a2)), "r"(__float_as_uint(a3)),
          "r"(__float_as_uint(b0)), "r"(__float_as_uint(b1)));
}
__device__ __forceinline__ float4 ldcg4(const float4* p) {
    float4 v;
    asm volatile("ld.global.cg.v4.f32 {%0,%1,%2,%3}, [%4];"
                 : "=f"(v.x), "=f"(v.y), "=f"(v.z), "=f"(v.w) : "l"(p));
    return v;
}
// W fragments for one k-panel: 4 conflict-free LDS.64
__device__ __forceinline__ void load_w(float2* bq, const float2* Ws, int p, int gid, int ktid) {
    const float2* wrow = Ws + p * 128 + gid * 4 + ktid;
    bq[0] = wrow[0];
    bq[1] = wrow[32];
    bq[2] = wrow[64];
    bq[3] = wrow[96];
}
__device__ __forceinline__ void mma8(float (&acc)[2][4][4], const float4* f, const float2* bq) {
#pragma unroll
    for (int mt = 0; mt < 2; ++mt)
#pragma unroll
        for (int n = 0; n < 4; ++n)
            mma_tf32(acc[mt][n], f[mt].x, f[mt].y, f[mt].z, f[mt].w, bq[n].x, bq[n].y);
}
__device__ __forceinline__ void store_acc(float* zr, const float (&acc)[2][4][4],
                                          int rb, int gid, int ktid) {
#pragma unroll
    for (int mt = 0; mt < 2; ++mt)
#pragma unroll
        for (int n = 0; n < 4; ++n) {
            int r = rb + mt * 16 + gid, cb = n * 8 + 2 * ktid;
            *(float2*)(zr + r * ZR_STRIDE + cb)       = make_float2(acc[mt][n][0], acc[mt][n][1]);
            *(float2*)(zr + (r + 8) * ZR_STRIDE + cb) = make_float2(acc[mt][n][2], acc[mt][n][3]);
        }
}
__device__ __forceinline__ void load_add(const float* zr, float (&acc)[2][4][4],
                                         int rb, int gid, int ktid) {
#pragma unroll
    for (int mt = 0; mt < 2; ++mt)
#pragma unroll
        for (int n = 0; n < 4; ++n) {
            int r = rb + mt * 16 + gid, cb = n * 8 + 2 * ktid;
            float2 v0 = *(const float2*)(zr + r * ZR_STRIDE + cb);
            float2 v1 = *(const float2*)(zr + (r + 8) * ZR_STRIDE + cb);
            acc[mt][n][0] += v0.x; acc[mt][n][1] += v0.y;
            acc[mt][n][2] += v1.x; acc[mt][n][3] += v1.y;
        }
}
__device__ __forceinline__ float sigmoid_f(float z) {
    return 1.0f / (1.0f + __expf(-z));
}
__device__ __forceinline__ float tanh_f(float z) {
    return 1.0f - 2.0f / (1.0f + __expf(2.0f * z));
}

// ---------------- prep kernels ----------------
// Pack W into per-CTA mma-B-fragment order (tf32-rounded) + bias. (R4/R6-proven layout.)
__global__ void prep_w(const float* __restrict__ Wf, const float* __restrict__ bf,
                       const float* __restrict__ Wi, const float* __restrict__ bi,
                       const float* __restrict__ Wg, const float* __restrict__ bg,
                       const float* __restrict__ Wo, const float* __restrict__ bo) {
    int idx = blockIdx.x * blockDim.x + threadIdx.x;
    if (idx < NCTA * COLS) {
        int cta = idx / COLS, ncol = idx % COLS;
        int gate = ncol >> 3, cc = ncol & 7;
        const float* bsrc = gate == 0 ? bf : gate == 1 ? bi : gate == 2 ? bg : bo;
        g_bp[idx] = bsrc[cta * HPC + cc];
    }
    if (idx >= NCTA * CTA_W_F2) return;
    int cta  = idx / CTA_W_F2;
    int rem  = idx % CTA_W_F2;
    int gk   = rem >> 7;
    int r2   = rem & 127;
    int ncol = r2 >> 2;        // n*8 + gid
    int ktid = r2 & 3;
    int gate = ncol >> 3, cc = ncol & 7;
    int col  = cta * HPC + cc;
    int k0   = gk * 8;
    const float* Wsrc = gate == 0 ? Wf : gate == 1 ? Wi : gate == 2 ? Wg : Wo;
    float v0 = Wsrc[(size_t)(k0 + ktid) * HID + col];
    float v1 = Wsrc[(size_t)(k0 + ktid + 4) * HID + col];
    g_Wp[idx] = make_float2(tf32r(v0), tf32r(v1));
}

// Permute x into fragment-order float4 slots, tf32-rounded. (R4-proven.)
__global__ void prep_xp(const float* __restrict__ x) {
    __shared__ float tile[16 * 132];
    int bid = blockIdx.x;
    int mt = bid & 3, kg = (bid >> 2) & 3, t = bid >> 4;
    const float* src = x + (size_t)t * BATCH * IN_DIM + (size_t)(mt * 16) * IN_DIM + kg * 128;
    for (int i = threadIdx.x; i < 16 * 32; i += 256) {
        int r = i >> 5, c4 = (i & 31) * 4;
        float4 v = *(const float4*)(src + (size_t)r * IN_DIM + c4);
        tile[r * 132 + c4]     = v.x;
        tile[r * 132 + c4 + 1] = v.y;
        tile[r * 132 + c4 + 2] = v.z;
        tile[r * 132 + c4 + 3] = v.w;
    }
    __syncthreads();
    for (int o = threadIdx.x; o < 512; o += 256) {
        int pl = o >> 5, l = o & 31;
        int gid = l >> 2, kt = l & 3;
        int k0 = pl * 8;
        float4 v;
        v.x = tf32r(tile[gid * 132 + k0 + kt]);
        v.y = tf32r(tile[(gid + 8) * 132 + k0 + kt]);
        v.z = tf32r(tile[gid * 132 + k0 + kt + 4]);
        v.w = tf32r(tile[(gid + 8) * 132 + k0 + kt + 4]);
        g_xp[(size_t)(t * 64 + kg * 16 + pl) * 128 + mt * 32 + l] = v;
    }
}

__global__ void init_k() {
    int i = blockIdx.x * blockDim.x + threadIdx.x;
    float* h = (float*)g_hp;
    if (i < 2 * 65536) h[i] = 0.0f;
    if (i < NCTA) g_flag[i] = 0u;
}

// ---------------- persistent LSTM kernel ----------------
__global__ void __launch_bounds__(512, 1) lstm_persist(float* __restrict__ out) {
    extern __shared__ char smem[];
    const float2* Ws = (const float2*)smem;               // 196608 B, fragment order
    float* zr = (float*)(smem + W_SMEM_B);                // 4 * ZR_BUF floats
    float* bias_s = (float*)(smem + W_SMEM_B + 4 * ZR_BUF * 4);

    const int tid = threadIdx.x, w = tid >> 5, lane = tid & 31;
    const int gid = lane >> 2, ktid = lane & 3;
    const int kw = w >> 1, mh = w & 1;            // k-split 8 x m-split 2
    const int aoff = mh * 64 + lane;
    const int rb = mh * 32;
    const int cta = blockIdx.x;

    {   // one-time W slice copy to smem (fragment order preserved)
        const float4* src = (const float4*)(g_Wp + (size_t)cta * CTA_W_F2);
        float4* dst = (float4*)smem;
        for (int i = tid; i < 12288; i += 512) dst[i] = src[i];
    }
    if (tid < COLS) bias_s[tid] = g_bp[cta * COLS + tid];
    __syncthreads();

    float creg = 0.0f;                            // cell state (1 elem/thread)
    const int px0 = kw * 8;                       // this warp's 8 x-panels
    const int ph0 = 64 + kw * 16;                 // this warp's 16 h-panels (W index)
    const unsigned* fp = g_flag + kw * 16 + (lane & 15);  // warp-wide flag poll

    float4 fr[3][2];
    {   // initial x prefetch for t=0
        const float4* xp = g_xp + (size_t)px0 * 128 + aoff;
        fr[0][0] = ldcg4(xp);       fr[0][1] = ldcg4(xp + 32);
        fr[1][0] = ldcg4(xp + 128); fr[1][1] = ldcg4(xp + 160);
    }

    for (int t = 0; t < TSTEPS; ++t) {
        float acc[2][4][4];
#pragma unroll
        for (int a = 0; a < 2; ++a)
#pragma unroll
            for (int b = 0; b < 4; ++b)
#pragma unroll
                for (int c = 0; c < 4; ++c) acc[a][b][c] = 0.0f;

        const float4* xpan = g_xp + (size_t)t * 8192 + (size_t)px0 * 128 + aoff;
        const float4* hpan = g_hp + (size_t)((t - 1) & 1) * 16384 + (size_t)(kw * 16) * 128 + aoff;

        float2 bq[2][4];
        // ---- X phase, panels 0..4 (loads panels 2..6; fr[0..1] preloaded) ----
        load_w(bq[0], Ws, px0, gid, ktid);
#pragma unroll
        for (int j = 0; j < 5; ++j) {
            const float4* p = xpan + (size_t)(j + 2) * 128;
            fr[(j + 2) % 3][0] = ldcg4(p);
            fr[(j + 2) % 3][1] = ldcg4(p + 32);
            load_w(bq[(j + 1) & 1], Ws, px0 + j + 1, gid, ktid);
            mma8(acc, fr[j % 3], bq[j & 1]);
        }
        // ---- x panel 5 (loads panel 7) ----
        {
            const float4* p = xpan + (size_t)7 * 128;
            fr[1][0] = ldcg4(p); fr[1][1] = ldcg4(p + 32);
            load_w(bq[0], Ws, px0 + 6, gid, ktid);
            mma8(acc, fr[2], bq[1]);
        }
        // ---- flag wait + h0 prefetch, hidden behind remaining 2 x panels ----
        if (t) {
            unsigned v;
            do {
                asm volatile("ld.acquire.gpu.global.u32 %0, [%1];"
                             : "=r"(v) : "l"(fp) : "memory");
            } while (__ballot_sync(0xffffffffu, v < (unsigned)t));
        }
        fr[2][0] = ldcg4(hpan); fr[2][1] = ldcg4(hpan + 32);          // h0 -> fr[2]
        // ---- x panel 6 ----
        load_w(bq[1], Ws, px0 + 7, gid, ktid);
        mma8(acc, fr[0], bq[0]);
        fr[0][0] = ldcg4(hpan + 128); fr[0][1] = ldcg4(hpan + 160);   // h1 -> fr[0]
        // ---- x panel 7 ----
        load_w(bq[0], Ws, ph0, gid, ktid);                            // first h W
        mma8(acc, fr[1], bq[1]);

        // ---- H phase: h panel j lives in fr[(j+2)%3] ----
#pragma unroll
        for (int j = 0; j < 16; ++j) {
            if (j < 14) {
                const float4* p = hpan + (size_t)(j + 2) * 128;
                fr[(j + 1) % 3][0] = ldcg4(p);       // (j+4)%3 == (j+1)%3
                fr[(j + 1) % 3][1] = ldcg4(p + 32);
            }
            if (j < 15) load_w(bq[(j + 1) & 1], Ws, ph0 + j + 1, gid, ktid);
            mma8(acc, fr[(j + 2) % 3], bq[j & 1]);
        }

        // ---- cross-step x prefetch (lands during reduce+epilogue; g_xp padded) ----
        {
            const float4* xn = g_xp + (size_t)(t + 1) * 8192 + (size_t)px0 * 128 + aoff;
            fr[0][0] = ldcg4(xn);       fr[0][1] = ldcg4(xn + 32);
            fr[1][0] = ldcg4(xn + 128); fr[1][1] = ldcg4(xn + 160);
        }

        // ---- 2-round k-partial reduction (8 -> 4 in smem, 4 -> 1 in epilogue) ----
        if (kw >= 4) store_acc(zr + (size_t)(kw - 4) * ZR_BUF, acc, rb, gid, ktid);
        __syncthreads();
        if (kw < 4) {
            load_add(zr + (size_t)kw * ZR_BUF, acc, rb, gid, ktid);
            store_acc(zr + (size_t)kw * ZR_BUF, acc, rb, gid, ktid);
        }
        __syncthreads();

        // ---- fused gate epilogue: 512 elements, 1 per thread; sums 4 bufs ----
        {
            int b  = tid >> 3, cx = tid & 7;
            float zf = bias_s[cx], zi = bias_s[8 + cx];
            float zg = bias_s[16 + cx], zo = bias_s[24 + cx];
#pragma unroll
            for (int u = 0; u < 4; ++u) {
                const float* zb = zr + u * ZR_BUF + b * ZR_STRIDE;
                zf += zb[cx];
                zi += zb[8 + cx];
                zg += zb[16 + cx];
                zo += zb[24 + cx];
            }
            float fg = sigmoid_f(zf);
            float ig = sigmoid_f(zi);
            float gg = tanh_f(zg);
            float og = sigmoid_f(zo);
            float cn = fg * creg + ig * gg;
            creg = cn;
            float h = og * tanh_f(cn);
            int hcol = cta * HPC + cx;
            out[(size_t)t * (BATCH * HID) + b * HID + hcol] = h;
            // fragment-permuted tf32 h for next step's A operand
            int p   = hcol >> 3, j = hcol & 7;
            int mt  = b >> 4, g8 = b & 7, hh = (b >> 3) & 1;
            int kt2 = j & 3, comp = ((j >> 2) << 1) | hh;
            ((float*)g_hp)[((size_t)(t & 1) * 16384 + (size_t)(p * 4 + mt) * 32 +
                            g8 * 4 + kt2) * 4 + comp] = tf32r(h);
            if (t == TSTEPS - 1) {
                size_t tail = (size_t)TSTEPS * BATCH * HID;
                out[tail + b * HID + hcol] = h;
                out[tail + BATCH * HID + b * HID + hcol] = cn;
            }
        }
        __syncthreads();   // h writes of all threads done; zr reusable

        // ---- publish h_t (release flag; consumers acquire) ----
        if (tid == 0) {
            __threadfence();
            asm volatile("st.release.gpu.global.u32 [%0], %1;"
                         :: "l"(g_flag + cta), "r"((unsigned)(t + 1)) : "memory");
        }
    }
}

// ---------------- host ----------------
extern "C" void kernel_launch(void* const* d_in, const int* in_sizes, int n_in,
                              void* d_out, int out_size) {
    const float* x  = (const float*)d_in[0];
    const float* Wf = (const float*)d_in[1];
    const float* bf = (const float*)d_in[2];
    const float* Wi = (const float*)d_in[3];
    const float* bi = (const float*)d_in[4];
    const float* Wg = (const float*)d_in[5];
    const float* bg = (const float*)d_in[6];
    const float* Wo = (const float*)d_in[7];
    const float* bo = (const float*)d_in[8];
    float* out = (float*)d_out;

    static int attr_done = 0;
    if (!attr_done) {
        cudaFuncSetAttribute(lstm_persist, cudaFuncAttributeMaxDynamicSharedMemorySize,
                             SMEM_BYTES);
        attr_done = 1;
    }

    init_k<<<512, 256>>>();
    prep_w<<<(NCTA * CTA_W_F2 + 255) / 256, 256>>>(Wf, bf, Wi, bi, Wg, bg, Wo, bo);
    prep_xp<<<8192, 256>>>(x);
    lstm_persist<<<NCTA, 512, SMEM_BYTES>>>(out);
}

// round 14
// speedup vs baseline: 2.7769x; 1.3024x over previous
#include <cuda_runtime.h>
#include <cstdint>

#define TSTEPS  512
#define BATCH   64
#define IN_DIM  512
#define HID     1024
#define NCTA    128
#define COLS    32                 // z-cols per CTA = 4 gates x 8 hid cols
#define HPC     8
#define CTA_W_F2 24576             // 192 kpanels * 128 float2
#define ZR_STRIDE 34
#define ZR_BUF   (64 * ZR_STRIDE)  // 2176 floats
#define W_SMEM_B 196608
#define SMEM_BYTES (W_SMEM_B + 4 * ZR_BUF * 4 + 128)   // 231552

// ---- static device scratch (no allocations) ----
__device__ float2   g_Wp[(size_t)NCTA * CTA_W_F2];     // packed tf32 W (~25MB)
__device__ float4   g_xp[(size_t)(TSTEPS + 1) * 8192]; // x, fragment-permuted (+1 step slack)
__device__ float4   g_hp[2 * 16384];                   // h, fragment-permuted, dbl-buffered
__device__ float    g_bp[NCTA * COLS];                 // packed bias
__device__ unsigned g_flag[NCTA];                      // per-CTA h-publication flags

// ---------------- helpers ----------------
__device__ __forceinline__ float tf32r(float x) {
    unsigned r;
    asm("cvt.rna.tf32.f32 %0, %1;" : "=r"(r) : "f"(x));
    return __uint_as_float(r);
}
__device__ __forceinline__ void mma_tf32(float* c, float a0, float a1, float a2, float a3,
                                         float b0, float b1) {
    asm volatile(
        "mma.sync.aligned.m16n8k8.row.col.f32.tf32.tf32.f32 "
        "{%0,%1,%2,%3},{%4,%5,%6,%7},{%8,%9},{%0,%1,%2,%3};"
        : "+f"(c[0]), "+f"(c[1]), "+f"(c[2]), "+f"(c[3])
        : "r"(__float_as_uint(a0)), "r"(__float_as_uint(a1)),
          "r"(__float_as_uint(a2)), "r"(__float_as_uint(a3)),
          "r"(__float_as_uint(b0)), "r"(__float_as_uint(b1)));
}
__device__ __forceinline__ float4 ldcg4(const float4* p) {
    float4 v;
    asm volatile("ld.global.cg.v4.f32 {%0,%1,%2,%3}, [%4];"
                 : "=f"(v.x), "=f"(v.y), "=f"(v.z), "=f"(v.w) : "l"(p));
    return v;
}
// W fragments for one k-panel: 4 conflict-free LDS.64
__device__ __forceinline__ void load_w(float2* bq, const float2* Ws, int p, int gid, int ktid) {
    const float2* wrow = Ws + p * 128 + gid * 4 + ktid;
    bq[0] = wrow[0];
    bq[1] = wrow[32];
    bq[2] = wrow[64];
    bq[3] = wrow[96];
}
__device__ __forceinline__ void mma8(float (&acc)[2][4][4], const float4* f, const float2* bq) {
#pragma unroll
    for (int mt = 0; mt < 2; ++mt)
#pragma unroll
        for (int n = 0; n < 4; ++n)
            mma_tf32(acc[mt][n], f[mt].x, f[mt].y, f[mt].z, f[mt].w, bq[n].x, bq[n].y);
}
__device__ __forceinline__ void store_acc(float* zr, const float (&acc)[2][4][4],
                                          int rb, int gid, int ktid) {
#pragma unroll
    for (int mt = 0; mt < 2; ++mt)
#pragma unroll
        for (int n = 0; n < 4; ++n) {
            int r = rb + mt * 16 + gid, cb = n * 8 + 2 * ktid;
            *(float2*)(zr + r * ZR_STRIDE + cb)       = make_float2(acc[mt][n][0], acc[mt][n][1]);
            *(float2*)(zr + (r + 8) * ZR_STRIDE + cb) = make_float2(acc[mt][n][2], acc[mt][n][3]);
        }
}
__device__ __forceinline__ void load_add(const float* zr, float (&acc)[2][4][4],
                                         int rb, int gid, int ktid) {
#pragma unroll
    for (int mt = 0; mt < 2; ++mt)
#pragma unroll
        for (int n = 0; n < 4; ++n) {
            int r = rb + mt * 16 + gid, cb = n * 8 + 2 * ktid;
            float2 v0 = *(const float2*)(zr + r * ZR_STRIDE + cb);
            float2 v1 = *(const float2*)(zr + (r + 8) * ZR_STRIDE + cb);
            acc[mt][n][0] += v0.x; acc[mt][n][1] += v0.y;
            acc[mt][n][2] += v1.x; acc[mt][n][3] += v1.y;
        }
}
__device__ __forceinline__ float sigmoid_f(float z) {
    return 1.0f / (1.0f + __expf(-z));
}
__device__ __forceinline__ float tanh_f(float z) {
    return 1.0f - 2.0f / (1.0f + __expf(2.0f * z));
}

// ---------------- prep kernels ----------------
// Pack W into per-CTA mma-B-fragment order (tf32-rounded) + bias. (R4/R6-proven layout.)
__global__ void prep_w(const float* __restrict__ Wf, const float* __restrict__ bf,
                       const float* __restrict__ Wi, const float* __restrict__ bi,
                       const float* __restrict__ Wg, const float* __restrict__ bg,
                       const float* __restrict__ Wo, const float* __restrict__ bo) {
    int idx = blockIdx.x * blockDim.x + threadIdx.x;
    if (idx < NCTA * COLS) {
        int cta = idx / COLS, ncol = idx % COLS;
        int gate = ncol >> 3, cc = ncol & 7;
        const float* bsrc = gate == 0 ? bf : gate == 1 ? bi : gate == 2 ? bg : bo;
        g_bp[idx] = bsrc[cta * HPC + cc];
    }
    if (idx >= NCTA * CTA_W_F2) return;
    int cta  = idx / CTA_W_F2;
    int rem  = idx % CTA_W_F2;
    int gk   = rem >> 7;
    int r2   = rem & 127;
    int ncol = r2 >> 2;        // n*8 + gid
    int ktid = r2 & 3;
    int gate = ncol >> 3, cc = ncol & 7;
    int col  = cta * HPC + cc;
    int k0   = gk * 8;
    const float* Wsrc = gate == 0 ? Wf : gate == 1 ? Wi : gate == 2 ? Wg : Wo;
    float v0 = Wsrc[(size_t)(k0 + ktid) * HID + col];
    float v1 = Wsrc[(size_t)(k0 + ktid + 4) * HID + col];
    g_Wp[idx] = make_float2(tf32r(v0), tf32r(v1));
}

// Permute x into fragment-order float4 slots, tf32-rounded. (R4-proven.)
__global__ void prep_xp(const float* __restrict__ x) {
    __shared__ float tile[16 * 132];
    int bid = blockIdx.x;
    int mt = bid & 3, kg = (bid >> 2) & 3, t = bid >> 4;
    const float* src = x + (size_t)t * BATCH * IN_DIM + (size_t)(mt * 16) * IN_DIM + kg * 128;
    for (int i = threadIdx.x; i < 16 * 32; i += 256) {
        int r = i >> 5, c4 = (i & 31) * 4;
        float4 v = *(const float4*)(src + (size_t)r * IN_DIM + c4);
        tile[r * 132 + c4]     = v.x;
        tile[r * 132 + c4 + 1] = v.y;
        tile[r * 132 + c4 + 2] = v.z;
        tile[r * 132 + c4 + 3] = v.w;
    }
    __syncthreads();
    for (int o = threadIdx.x; o < 512; o += 256) {
        int pl = o >> 5, l = o & 31;
        int gid = l >> 2, kt = l & 3;
        int k0 = pl * 8;
        float4 v;
        v.x = tf32r(tile[gid * 132 + k0 + kt]);
        v.y = tf32r(tile[(gid + 8) * 132 + k0 + kt]);
        v.z = tf32r(tile[gid * 132 + k0 + kt + 4]);
        v.w = tf32r(tile[(gid + 8) * 132 + k0 + kt + 4]);
        g_xp[(size_t)(t * 64 + kg * 16 + pl) * 128 + mt * 32 + l] = v;
    }
}

__global__ void init_k() {
    int i = blockIdx.x * blockDim.x + threadIdx.x;
    float* h = (float*)g_hp;
    if (i < 2 * 65536) h[i] = 0.0f;
    if (i < NCTA) g_flag[i] = 0u;
}

// ---------------- persistent LSTM kernel ----------------
__global__ void __launch_bounds__(512, 1) lstm_persist(float* __restrict__ out) {
    extern __shared__ char smem[];
    const float2* Ws = (const float2*)smem;               // 196608 B, fragment order
    float* zr = (float*)(smem + W_SMEM_B);                // 4 * ZR_BUF floats
    float* bias_s = (float*)(smem + W_SMEM_B + 4 * ZR_BUF * 4);

    const int tid = threadIdx.x, w = tid >> 5, lane = tid & 31;
    const int gid = lane >> 2, ktid = lane & 3;
    const int kw = w >> 1, mh = w & 1;            // k-split 8 x m-split 2
    const int aoff = mh * 64 + lane;              // A m-half offset
    const int rb = mh * 32;                       // reduce row base
    const int cta = blockIdx.x;

    {   // one-time W slice copy to smem (fragment order preserved)
        const float4* src = (const float4*)(g_Wp + (size_t)cta * CTA_W_F2);
        float4* dst = (float4*)smem;
        for (int i = tid; i < 12288; i += 512) dst[i] = src[i];
    }
    if (tid < COLS) bias_s[tid] = g_bp[cta * COLS + tid];
    __syncthreads();

    // epilogue element mapping chosen so the g_hp store index == tid (coalesced):
    //   e = mt*128 + g8*16 + kt2*4 + c2*2 + hh ; b = mt*16 + hh*8 + g8 ; cx = c2*4 + kt2
    const int e_hh  = tid & 1;
    const int e_c2  = (tid >> 1) & 1;
    const int e_kt2 = (tid >> 2) & 3;
    const int e_g8  = (tid >> 4) & 7;
    const int e_mt  = (tid >> 7) & 3;
    const int eb = e_mt * 16 + e_hh * 8 + e_g8;   // batch row
    const int ec = e_c2 * 4 + e_kt2;              // hid col within CTA

    float creg = 0.0f;                            // cell state (1 elem/thread)
    const int px0 = kw * 8;                       // this warp's 8 x-panels
    const int ph0 = 64 + kw * 16;                 // this warp's 16 h-panels (W index)
    const unsigned* fp = g_flag + kw * 16 + (lane & 15);  // warp-wide flag poll

    float4 fr[3][2];
    {   // initial x prefetch for t=0
        const float4* xp = g_xp + (size_t)px0 * 128 + aoff;
        fr[0][0] = ldcg4(xp);       fr[0][1] = ldcg4(xp + 32);
        fr[1][0] = ldcg4(xp + 128); fr[1][1] = ldcg4(xp + 160);
    }

    for (int t = 0; t < TSTEPS; ++t) {
        float acc[2][4][4];
#pragma unroll
        for (int a = 0; a < 2; ++a)
#pragma unroll
            for (int b = 0; b < 4; ++b)
#pragma unroll
                for (int c = 0; c < 4; ++c) acc[a][b][c] = 0.0f;

        const float4* xpan = g_xp + (size_t)t * 8192 + (size_t)px0 * 128 + aoff;
        const float4* hpan = g_hp + (size_t)((t - 1) & 1) * 16384 + (size_t)(kw * 16) * 128 + aoff;

        float2 bq[2][4];
        // ---- X phase (no h dependency; overlaps producer skew). fr[0..1] preloaded. ----
        load_w(bq[0], Ws, px0, gid, ktid);
#pragma unroll
        for (int j = 0; j < 8; ++j) {
            if (j < 6) {
                const float4* p = xpan + (size_t)(j + 2) * 128;
                fr[(j + 2) % 3][0] = ldcg4(p);
                fr[(j + 2) % 3][1] = ldcg4(p + 32);
            }
            if (j < 7) load_w(bq[(j + 1) & 1], Ws, px0 + j + 1, gid, ktid);
            mma8(acc, fr[j % 3], bq[j & 1]);
        }

        // ---- per-warp dataflow wait: h-panels kw*16..+16 produced by 16 CTAs ----
        if (t) {
            unsigned v;
            do {
                asm volatile("ld.acquire.gpu.global.u32 %0, [%1];"
                             : "=r"(v) : "l"(fp) : "memory");
            } while (__ballot_sync(0xffffffffu, v < (unsigned)t));
        }

        // ---- H phase ----
        fr[0][0] = ldcg4(hpan);       fr[0][1] = ldcg4(hpan + 32);
        fr[1][0] = ldcg4(hpan + 128); fr[1][1] = ldcg4(hpan + 160);
        load_w(bq[0], Ws, ph0, gid, ktid);
#pragma unroll
        for (int j = 0; j < 16; ++j) {
            if (j < 14) {
                const float4* p = hpan + (size_t)(j + 2) * 128;
                fr[(j + 2) % 3][0] = ldcg4(p);
                fr[(j + 2) % 3][1] = ldcg4(p + 32);
            }
            if (j < 15) load_w(bq[(j + 1) & 1], Ws, ph0 + j + 1, gid, ktid);
            mma8(acc, fr[j % 3], bq[j & 1]);
        }

        // ---- cross-step x prefetch (lands during reduce+epilogue; g_xp padded) ----
        {
            const float4* xn = g_xp + (size_t)(t + 1) * 8192 + (size_t)px0 * 128 + aoff;
            fr[0][0] = ldcg4(xn);       fr[0][1] = ldcg4(xn + 32);
            fr[1][0] = ldcg4(xn + 128); fr[1][1] = ldcg4(xn + 160);
        }

        // ---- 2-round k-partial reduction (8 -> 4 in smem, 4 -> 1 in epilogue) ----
        if (kw >= 4) store_acc(zr + (size_t)(kw - 4) * ZR_BUF, acc, rb, gid, ktid);
        __syncthreads();
        if (kw < 4) {
            load_add(zr + (size_t)kw * ZR_BUF, acc, rb, gid, ktid);
            store_acc(zr + (size_t)kw * ZR_BUF, acc, rb, gid, ktid);
        }
        __syncthreads();

        // ---- fused gate epilogue: 512 elements, 1 per thread; sums 4 bufs ----
        {
            float zf = bias_s[ec], zi = bias_s[8 + ec];
            float zg = bias_s[16 + ec], zo = bias_s[24 + ec];
#pragma unroll
            for (int u = 0; u < 4; ++u) {
                const float* zb = zr + u * ZR_BUF + eb * ZR_STRIDE;
                zf += zb[ec];
                zi += zb[8 + ec];
                zg += zb[16 + ec];
                zo += zb[24 + ec];
            }
            float fg = sigmoid_f(zf);
            float ig = sigmoid_f(zi);
            float gg = tanh_f(zg);
            float og = sigmoid_f(zo);
            float cn = fg * creg + ig * gg;
            creg = cn;
            float h = og * tanh_f(cn);
            int hcol = cta * HPC + ec;
            out[(size_t)t * (BATCH * HID) + eb * HID + hcol] = h;
            // fragment-permuted tf32 h: with this thread mapping the float index == tid
            ((float*)g_hp)[(size_t)(t & 1) * 65536 + (size_t)cta * 512 + tid] = tf32r(h);
            if (t == TSTEPS - 1) {
                size_t tail = (size_t)TSTEPS * BATCH * HID;
                out[tail + eb * HID + hcol] = h;
                out[tail + BATCH * HID + eb * HID + hcol] = cn;
            }
        }
        __syncthreads();   // h writes of all threads done; zr reusable

        // ---- publish h_t (release flag; consumers acquire) ----
        if (tid == 0) {
            __threadfence();
            asm volatile("st.release.gpu.global.u32 [%0], %1;"
                         :: "l"(g_flag + cta), "r"((unsigned)(t + 1)) : "memory");
        }
    }
}

// ---------------- host ----------------
extern "C" void kernel_launch(void* const* d_in, const int* in_sizes, int n_in,
                              void* d_out, int out_size) {
    const float* x  = (const float*)d_in[0];
    const float* Wf = (const float*)d_in[1];
    const float* bf = (const float*)d_in[2];
    const float* Wi = (const float*)d_in[3];
    const float* bi = (const float*)d_in[4];
    const float* Wg = (const float*)d_in[5];
    const float* bg = (const float*)d_in[6];
    const float* Wo = (const float*)d_in[7];
    const float* bo = (const float*)d_in[8];
    float* out = (float*)d_out;

    static int attr_done = 0;
    if (!attr_done) {
        cudaFuncSetAttribute(lstm_persist, cudaFuncAttributeMaxDynamicSharedMemorySize,
                             SMEM_BYTES);
        attr_done = 1;
    }

    init_k<<<512, 256>>>();
    prep_w<<<(NCTA * CTA_W_F2 + 255) / 256, 256>>>(Wf, bf, Wi, bi, Wg, bg, Wo, bo);
    prep_xp<<<8192, 256>>>(x);
    lstm_persist<<<NCTA, 512, SMEM_BYTES>>>(out);
}